// round 13
// baseline (speedup 1.0000x reference)
#include <cuda_runtime.h>
#include <cuda_bf16.h>
#include <math.h>
#include <stdint.h>

#define NODE_DIM   128
#define HIDDEN_DIM 64
#define MAX_N      100000

// Scratch UV in bf16: uv16[n][0:64] = u = x[n]@W1[:128]+b1 ; [64:128] = v = x[n]@W1[128:]
__device__ __nv_bfloat16 g_uv16[(size_t)MAX_N * NODE_DIM];
// Prebaked Weff in bf16, smem image layout: rows k=0..127, stride 136 bf16 (34 uint2)
__device__ uint2 g_weff[128 * 34];

// ---------------------------------------------------------------------------
// PTX helpers
// ---------------------------------------------------------------------------
__device__ __forceinline__ uint32_t smem_u32(const void* p) {
    return (uint32_t)__cvta_generic_to_shared(p);
}
__device__ __forceinline__ void ldsm_x4(uint32_t* r, uint32_t addr) {
    asm volatile("ldmatrix.sync.aligned.m8n8.x4.shared.b16 {%0,%1,%2,%3}, [%4];"
                 : "=r"(r[0]), "=r"(r[1]), "=r"(r[2]), "=r"(r[3]) : "r"(addr));
}
__device__ __forceinline__ void ldsm_x4_t(uint32_t* r, uint32_t addr) {
    asm volatile("ldmatrix.sync.aligned.m8n8.x4.trans.shared.b16 {%0,%1,%2,%3}, [%4];"
                 : "=r"(r[0]), "=r"(r[1]), "=r"(r[2]), "=r"(r[3]) : "r"(addr));
}
__device__ __forceinline__ void mma16816(float* c, const uint32_t* a,
                                         uint32_t b0, uint32_t b1) {
    asm volatile(
        "mma.sync.aligned.m16n8k16.row.col.f32.bf16.bf16.f32 "
        "{%0,%1,%2,%3}, {%4,%5,%6,%7}, {%8,%9}, {%0,%1,%2,%3};"
        : "+f"(c[0]), "+f"(c[1]), "+f"(c[2]), "+f"(c[3])
        : "r"(a[0]), "r"(a[1]), "r"(a[2]), "r"(a[3]), "r"(b0), "r"(b1));
}
// pack float4 -> 2x bf162 (8 bytes)
__device__ __forceinline__ uint2 pack4(float4 v) {
    __nv_bfloat162 h01 = __floats2bfloat162_rn(v.x, v.y);
    __nv_bfloat162 h23 = __floats2bfloat162_rn(v.z, v.w);
    return make_uint2(*(uint32_t*)&h01, *(uint32_t*)&h23);
}

// ---------------------------------------------------------------------------
// Kernel 0: wprep — bake Weff bf16 (smem image incl. pad cols) once.
//   Weff[k][c] = (c < 64) ? W1[k*64 + c] : W1[(128+k)*64 + (c-64)]
// ---------------------------------------------------------------------------
__global__ void wprep_kernel(const float* __restrict__ W1)
{
    int i = blockIdx.x * blockDim.x + threadIdx.x;   // 0..4351
    if (i >= 128 * 34) return;
    int k  = i / 34;
    int c4 = i % 34;
    uint2 val = make_uint2(0u, 0u);
    if (c4 < 32) {
        const float* src = (c4 < 16) ? (W1 + k * 64 + c4 * 4)
                                     : (W1 + (128 + k) * 64 + (c4 - 16) * 4);
        val = pack4(*(const float4*)src);
    }
    g_weff[i] = val;
}

// ---------------------------------------------------------------------------
// Kernel 1: persistent node GEMM, bf16 mma.sync, fp32 acc (R11 config,
// W staging = straight bf16 copy from g_weff).
// 70 KB smem -> 3 blocks/SM. A-tile buffer unioned with epilogue staging.
// ---------------------------------------------------------------------------
#define GEMM_GRID 444
#define PAD_COLS  136
#define EPI_WORDS 68
#define AB_BYTES  (128 * PAD_COLS * 2)    // 34816
#define OFF_B     0
#define OFF_AE    AB_BYTES
#define OFF_B1S   (2 * AB_BYTES)
#define GEMM_SMEM (2 * AB_BYTES + 256)    // 69888

__global__ __launch_bounds__(256)
void node_gemm_persistent(const float* __restrict__ x,
                          const float* __restrict__ b1,
                          int n, int tiles)
{
    extern __shared__ char sm[];
    __nv_bfloat16* Bh  = (__nv_bfloat16*)(sm + OFF_B);
    __nv_bfloat16* Ah  = (__nv_bfloat16*)(sm + OFF_AE);   // union with Epi
    uint32_t*      Epi = (uint32_t*)(sm + OFF_AE);
    float*         b1s = (float*)(sm + OFF_B1S);

    const int t    = threadIdx.x;
    const int warp = t >> 5;
    const int lane = t & 31;

    // ---- stage Weff bf16 (straight copy of prebaked image) + bias ----
    for (int i = t; i < 128 * 34; i += 256)
        ((uint2*)Bh)[i] = g_weff[i];
    if (t < 64) b1s[t] = b1[t];

    const uint32_t ROWB = PAD_COLS * 2;
    const uint32_t a_base = smem_u32(Ah) +
        (uint32_t)(((warp * 16 + (lane & 15)) * PAD_COLS + (lane >> 4) * 8) * 2);
    const uint32_t b_base = smem_u32(Bh) +
        (uint32_t)(((lane & 15) * PAD_COLS + (lane >> 4) * 8) * 2);

    const int r0  = lane >> 2;
    const int cqh = lane & 3;

    for (int tile = blockIdx.x; tile < tiles; tile += GEMM_GRID) {
        const int node0 = tile * 128;

        __syncthreads();   // prior STG reads of Epi done

        // ---- stage A: LDG float4 -> pack bf16 -> STS ----
#pragma unroll
        for (int it = 0; it < 16; it++) {
            int idx  = t + it * 256;
            int row  = idx >> 5;
            int c4   = idx & 31;
            int node = node0 + row;
            float4 v = (node < n) ? ((const float4*)x)[(size_t)node * 32 + c4]
                                  : make_float4(0.f, 0.f, 0.f, 0.f);
            *(uint2*)(Ah + row * PAD_COLS + c4 * 4) = pack4(v);
        }
        __syncthreads();

        // ---- compute: 128 HMMA per warp ----
        float acc[16][4];
#pragma unroll
        for (int i = 0; i < 16; i++)
#pragma unroll
            for (int j = 0; j < 4; j++) acc[i][j] = 0.f;

#pragma unroll
        for (int ks = 0; ks < 8; ks++) {
            uint32_t ah[4];
            ldsm_x4(ah, a_base + ks * 32);
#pragma unroll
            for (int j = 0; j < 8; j++) {
                uint32_t bh[4];
                ldsm_x4_t(bh, b_base + ks * 16 * ROWB + j * 32);
                mma16816(acc[2 * j],     ah, bh[0], bh[1]);
                mma16816(acc[2 * j + 1], ah, bh[2], bh[3]);
            }
        }
        __syncthreads();   // A reads done -> reuse as Epi

        // ---- epilogue: + bias, STS into Epi ----
        {
            const int lr0 = warp * 16 + r0;
            const int lr1 = lr0 + 8;
#pragma unroll
            for (int nt = 0; nt < 16; nt++) {
                int col = nt * 8 + cqh * 2;
                float bx = (col < 64) ? b1s[col] : 0.f;
                float by = (col < 64) ? b1s[col + 1] : 0.f;
                __nv_bfloat162 p0 = __floats2bfloat162_rn(acc[nt][0] + bx, acc[nt][1] + by);
                __nv_bfloat162 p1 = __floats2bfloat162_rn(acc[nt][2] + bx, acc[nt][3] + by);
                Epi[lr0 * EPI_WORDS + nt * 4 + cqh] = *(uint32_t*)&p0;
                Epi[lr1 * EPI_WORDS + nt * 4 + cqh] = *(uint32_t*)&p1;
            }
        }
        __syncthreads();

        // ---- coalesced STG ----
#pragma unroll
        for (int it = 0; it < 8; it++) {
            int idx  = t + it * 256;
            int row  = idx >> 4;
            int wq   = idx & 15;
            int node = node0 + row;
            if (node < n) {
                uint4 v = *(const uint4*)(Epi + row * EPI_WORDS + wq * 4);
                *(uint4*)(g_uv16 + (size_t)node * 128 + wq * 8) = v;
            }
        }
    }
}

// ---------------------------------------------------------------------------
// Kernel 2: edge pass (R8/R12 layout). 8 lanes/edge, 16 edges/warp, MLP=8.
// Takes pre-offset row/col/out pointers so it can be launched per edge-range.
//   out[e] = sigmoid( relu(u[row] + v[col]) . W2 + b2 )
// ---------------------------------------------------------------------------
__device__ __forceinline__ float edge_dot(uint4 u, uint4 v, float4 wa, float4 wb)
{
    const __nv_bfloat162 z2 = __float2bfloat162_rn(0.f);
    __nv_bfloat162 h0 = __hmax2(__hadd2(*(__nv_bfloat162*)&u.x, *(__nv_bfloat162*)&v.x), z2);
    __nv_bfloat162 h1 = __hmax2(__hadd2(*(__nv_bfloat162*)&u.y, *(__nv_bfloat162*)&v.y), z2);
    __nv_bfloat162 h2 = __hmax2(__hadd2(*(__nv_bfloat162*)&u.z, *(__nv_bfloat162*)&v.z), z2);
    __nv_bfloat162 h3 = __hmax2(__hadd2(*(__nv_bfloat162*)&u.w, *(__nv_bfloat162*)&v.w), z2);
    float2 f0 = __bfloat1622float2(h0);
    float2 f1 = __bfloat1622float2(h1);
    float2 f2 = __bfloat1622float2(h2);
    float2 f3 = __bfloat1622float2(h3);
    float p = f0.x * wa.x;
    p = fmaf(f0.y, wa.y, p);
    p = fmaf(f1.x, wa.z, p);
    p = fmaf(f1.y, wa.w, p);
    p = fmaf(f2.x, wb.x, p);
    p = fmaf(f2.y, wb.y, p);
    p = fmaf(f3.x, wb.z, p);
    p = fmaf(f3.y, wb.w, p);
    return p;
}

#define EDGE_THREADS 128

__global__ __launch_bounds__(EDGE_THREADS)
void edge_kernel(const int* __restrict__ rows,
                 const int* __restrict__ cols,
                 const float* __restrict__ W2,
                 const float* __restrict__ b2,
                 float* __restrict__ out,
                 int count)
{
    const int warp_id = (blockIdx.x * blockDim.x + threadIdx.x) >> 5;
    const int lane = threadIdx.x & 31;
    const int g  = lane >> 3;
    const int gl = lane & 7;

    const long long base = (long long)warp_id * 16 + g * 4;
    if (base >= count) return;   // count % 4 == 0: group of 4 valid together

    const int4 rr = *(const int4*)(rows + base);
    const int4 cc = *(const int4*)(cols + base);

    const size_t o = (size_t)gl * 8;
    const uint4 u0 = *(const uint4*)(g_uv16 + (size_t)rr.x * 128 + o);
    const uint4 v0 = *(const uint4*)(g_uv16 + (size_t)cc.x * 128 + 64 + o);
    const uint4 u1 = *(const uint4*)(g_uv16 + (size_t)rr.y * 128 + o);
    const uint4 v1 = *(const uint4*)(g_uv16 + (size_t)cc.y * 128 + 64 + o);
    const uint4 u2 = *(const uint4*)(g_uv16 + (size_t)rr.z * 128 + o);
    const uint4 v2 = *(const uint4*)(g_uv16 + (size_t)cc.z * 128 + 64 + o);
    const uint4 u3 = *(const uint4*)(g_uv16 + (size_t)rr.w * 128 + o);
    const uint4 v3 = *(const uint4*)(g_uv16 + (size_t)cc.w * 128 + 64 + o);

    const float4 wa = __ldg((const float4*)W2 + gl * 2);
    const float4 wb = __ldg((const float4*)W2 + gl * 2 + 1);

    float p0 = edge_dot(u0, v0, wa, wb);
    float p1 = edge_dot(u1, v1, wa, wb);
    float p2 = edge_dot(u2, v2, wa, wb);
    float p3 = edge_dot(u3, v3, wa, wb);

#pragma unroll
    for (int off = 4; off > 0; off >>= 1) {
        p0 += __shfl_down_sync(0xFFFFFFFFu, p0, off, 8);
        p1 += __shfl_down_sync(0xFFFFFFFFu, p1, off, 8);
        p2 += __shfl_down_sync(0xFFFFFFFFu, p2, off, 8);
        p3 += __shfl_down_sync(0xFFFFFFFFu, p3, off, 8);
    }

    if (gl == 0) {
        float bb = __ldg(b2);
        float4 oo;
        oo.x = 1.0f / (1.0f + __expf(-(p0 + bb)));
        oo.y = 1.0f / (1.0f + __expf(-(p1 + bb)));
        oo.z = 1.0f / (1.0f + __expf(-(p2 + bb)));
        oo.w = 1.0f / (1.0f + __expf(-(p3 + bb)));
        *(float4*)(out + base) = oo;
    }
}

// ---------------------------------------------------------------------------
// Launch pattern is 4-periodic (wprep, gemm, edge1, edge2) so the fixed ncu
// capture (-s 5) lands on the GEMM: 5 mod 4 = 1.
// ---------------------------------------------------------------------------
extern "C" void kernel_launch(void* const* d_in, const int* in_sizes, int n_in,
                              void* d_out, int out_size)
{
    const float* x          = (const float*)d_in[0];
    const int*   edge_index = (const int*)d_in[1];
    const float* W1         = (const float*)d_in[2];
    const float* b1         = (const float*)d_in[3];
    const float* W2         = (const float*)d_in[4];
    const float* b2         = (const float*)d_in[5];
    float*       out        = (float*)d_out;

    const int n = in_sizes[0] / NODE_DIM;   // 100000
    const int E = in_sizes[1] / 2;          // 625000
    const int tiles = (n + 127) / 128;      // 782
    const int Eh = E / 2;                   // 312500 (div by 4)

    cudaFuncSetAttribute(node_gemm_persistent,
                         cudaFuncAttributeMaxDynamicSharedMemorySize,
                         (int)GEMM_SMEM);

    // 0: wprep
    wprep_kernel<<<17, 256>>>(W1);

    // 1: GEMM
    node_gemm_persistent<<<GEMM_GRID, 256, GEMM_SMEM>>>(x, b1, n, tiles);

    // 2,3: edge halves
    const int wpb = EDGE_THREADS / 32;                         // 4
    const int warps_h = (Eh + 15) / 16;                        // 19532
    const int blocks_h = (warps_h + wpb - 1) / wpb;            // 4883
    edge_kernel<<<blocks_h, EDGE_THREADS>>>(edge_index,      edge_index + E,      W2, b2, out,      Eh);
    edge_kernel<<<blocks_h, EDGE_THREADS>>>(edge_index + Eh, edge_index + E + Eh, W2, b2, out + Eh, E - Eh);
}

// round 14
// speedup vs baseline: 1.0447x; 1.0447x over previous
#include <cuda_runtime.h>
#include <cuda_bf16.h>
#include <math.h>
#include <stdint.h>

#define NODE_DIM   128
#define HIDDEN_DIM 64
#define MAX_N      100000

// Scratch UV in bf16: uv16[n][0:64] = u = x[n]@W1[:128]+b1 ; [64:128] = v = x[n]@W1[128:]
__device__ __nv_bfloat16 g_uv16[(size_t)MAX_N * NODE_DIM];

// ---------------------------------------------------------------------------
// PTX helpers
// ---------------------------------------------------------------------------
__device__ __forceinline__ uint32_t smem_u32(const void* p) {
    return (uint32_t)__cvta_generic_to_shared(p);
}
__device__ __forceinline__ void ldsm_x4(uint32_t* r, uint32_t addr) {
    asm volatile("ldmatrix.sync.aligned.m8n8.x4.shared.b16 {%0,%1,%2,%3}, [%4];"
                 : "=r"(r[0]), "=r"(r[1]), "=r"(r[2]), "=r"(r[3]) : "r"(addr));
}
__device__ __forceinline__ void ldsm_x4_t(uint32_t* r, uint32_t addr) {
    asm volatile("ldmatrix.sync.aligned.m8n8.x4.trans.shared.b16 {%0,%1,%2,%3}, [%4];"
                 : "=r"(r[0]), "=r"(r[1]), "=r"(r[2]), "=r"(r[3]) : "r"(addr));
}
__device__ __forceinline__ void mma16816(float* c, const uint32_t* a,
                                         uint32_t b0, uint32_t b1) {
    asm volatile(
        "mma.sync.aligned.m16n8k16.row.col.f32.bf16.bf16.f32 "
        "{%0,%1,%2,%3}, {%4,%5,%6,%7}, {%8,%9}, {%0,%1,%2,%3};"
        : "+f"(c[0]), "+f"(c[1]), "+f"(c[2]), "+f"(c[3])
        : "r"(a[0]), "r"(a[1]), "r"(a[2]), "r"(a[3]), "r"(b0), "r"(b1));
}
// pack float4 -> 2x bf162 (8 bytes)
__device__ __forceinline__ uint2 pack4(float4 v) {
    __nv_bfloat162 h01 = __floats2bfloat162_rn(v.x, v.y);
    __nv_bfloat162 h23 = __floats2bfloat162_rn(v.z, v.w);
    return make_uint2(*(uint32_t*)&h01, *(uint32_t*)&h23);
}

// ---------------------------------------------------------------------------
// Kernel 1: persistent node GEMM, bf16 mma.sync, fp32 acc (R11 config).
//   UV (N,128) = X (N,128) @ Weff (128,128) + bias(cols 0..63), stored bf16
// x loaded with __ldcs (evict-first streaming): x is read exactly once, and
// keeping it out of L2 preserves residency for the UV the edge pass gathers.
// 70 KB smem -> 3 blocks/SM. A-tile buffer unioned with epilogue staging.
// ---------------------------------------------------------------------------
#define GEMM_GRID 444
#define PAD_COLS  136
#define EPI_WORDS 68
#define AB_BYTES  (128 * PAD_COLS * 2)    // 34816
#define OFF_B     0
#define OFF_AE    AB_BYTES
#define OFF_B1S   (2 * AB_BYTES)
#define GEMM_SMEM (2 * AB_BYTES + 256)    // 69888

__global__ __launch_bounds__(256)
void node_gemm_persistent(const float* __restrict__ x,
                          const float* __restrict__ W1,
                          const float* __restrict__ b1,
                          int n, int tiles)
{
    extern __shared__ char sm[];
    __nv_bfloat16* Bh  = (__nv_bfloat16*)(sm + OFF_B);
    __nv_bfloat16* Ah  = (__nv_bfloat16*)(sm + OFF_AE);   // union with Epi
    uint32_t*      Epi = (uint32_t*)(sm + OFF_AE);
    float*         b1s = (float*)(sm + OFF_B1S);

    const int t    = threadIdx.x;
    const int warp = t >> 5;
    const int lane = t & 31;

    // ---- stage Weff bf16 + bias (once per block; W1 small, L2-resident) ----
    for (int i = t; i < 128 * 32; i += 256) {
        int k  = i >> 5;
        int c4 = i & 31;
        const float* src = (c4 < 16) ? (W1 + k * 64 + c4 * 4)
                                     : (W1 + (128 + k) * 64 + (c4 - 16) * 4);
        float4 v = *(const float4*)src;
        *(uint2*)(Bh + k * PAD_COLS + c4 * 4) = pack4(v);
    }
    if (t < 64) b1s[t] = b1[t];

    const uint32_t ROWB = PAD_COLS * 2;
    const uint32_t a_base = smem_u32(Ah) +
        (uint32_t)(((warp * 16 + (lane & 15)) * PAD_COLS + (lane >> 4) * 8) * 2);
    const uint32_t b_base = smem_u32(Bh) +
        (uint32_t)(((lane & 15) * PAD_COLS + (lane >> 4) * 8) * 2);

    const int r0  = lane >> 2;
    const int cqh = lane & 3;

    for (int tile = blockIdx.x; tile < tiles; tile += GEMM_GRID) {
        const int node0 = tile * 128;

        __syncthreads();   // prior STG reads of Epi done

        // ---- stage A: streaming LDG float4 -> pack bf16 -> STS ----
#pragma unroll
        for (int it = 0; it < 16; it++) {
            int idx  = t + it * 256;
            int row  = idx >> 5;
            int c4   = idx & 31;
            int node = node0 + row;
            float4 v = (node < n)
                ? __ldcs(((const float4*)x) + (size_t)node * 32 + c4)
                : make_float4(0.f, 0.f, 0.f, 0.f);
            *(uint2*)(Ah + row * PAD_COLS + c4 * 4) = pack4(v);
        }
        __syncthreads();

        // ---- compute: 128 HMMA per warp ----
        float acc[16][4];
#pragma unroll
        for (int i = 0; i < 16; i++)
#pragma unroll
            for (int j = 0; j < 4; j++) acc[i][j] = 0.f;

#pragma unroll
        for (int ks = 0; ks < 8; ks++) {
            uint32_t ah[4];
            ldsm_x4(ah, a_base + ks * 32);
#pragma unroll
            for (int j = 0; j < 8; j++) {
                uint32_t bh[4];
                ldsm_x4_t(bh, b_base + ks * 16 * ROWB + j * 32);
                mma16816(acc[2 * j],     ah, bh[0], bh[1]);
                mma16816(acc[2 * j + 1], ah, bh[2], bh[3]);
            }
        }
        __syncthreads();   // A reads done -> reuse as Epi

        // ---- epilogue: + bias, STS into Epi ----
        {
            const int lr0 = warp * 16 + r0;
            const int lr1 = lr0 + 8;
#pragma unroll
            for (int nt = 0; nt < 16; nt++) {
                int col = nt * 8 + cqh * 2;
                float bx = (col < 64) ? b1s[col] : 0.f;
                float by = (col < 64) ? b1s[col + 1] : 0.f;
                __nv_bfloat162 p0 = __floats2bfloat162_rn(acc[nt][0] + bx, acc[nt][1] + by);
                __nv_bfloat162 p1 = __floats2bfloat162_rn(acc[nt][2] + bx, acc[nt][3] + by);
                Epi[lr0 * EPI_WORDS + nt * 4 + cqh] = *(uint32_t*)&p0;
                Epi[lr1 * EPI_WORDS + nt * 4 + cqh] = *(uint32_t*)&p1;
            }
        }
        __syncthreads();

        // ---- coalesced STG (default policy: keep UV in L2 for the edge pass) ----
#pragma unroll
        for (int it = 0; it < 8; it++) {
            int idx  = t + it * 256;
            int row  = idx >> 4;
            int wq   = idx & 15;
            int node = node0 + row;
            if (node < n) {
                uint4 v = *(const uint4*)(Epi + row * EPI_WORDS + wq * 4);
                *(uint4*)(g_uv16 + (size_t)node * 128 + wq * 8) = v;
            }
        }
    }
}

// ---------------------------------------------------------------------------
// Kernel 2: edge pass (R12 config). 8 lanes/edge, 16 edges/warp, MLP=8.
//   out[e] = sigmoid( relu(u[row] + v[col]) . W2 + b2 )
// ---------------------------------------------------------------------------
__device__ __forceinline__ float edge_dot(uint4 u, uint4 v, float4 wa, float4 wb)
{
    const __nv_bfloat162 z2 = __float2bfloat162_rn(0.f);
    __nv_bfloat162 h0 = __hmax2(__hadd2(*(__nv_bfloat162*)&u.x, *(__nv_bfloat162*)&v.x), z2);
    __nv_bfloat162 h1 = __hmax2(__hadd2(*(__nv_bfloat162*)&u.y, *(__nv_bfloat162*)&v.y), z2);
    __nv_bfloat162 h2 = __hmax2(__hadd2(*(__nv_bfloat162*)&u.z, *(__nv_bfloat162*)&v.z), z2);
    __nv_bfloat162 h3 = __hmax2(__hadd2(*(__nv_bfloat162*)&u.w, *(__nv_bfloat162*)&v.w), z2);
    float2 f0 = __bfloat1622float2(h0);
    float2 f1 = __bfloat1622float2(h1);
    float2 f2 = __bfloat1622float2(h2);
    float2 f3 = __bfloat1622float2(h3);
    float p = f0.x * wa.x;
    p = fmaf(f0.y, wa.y, p);
    p = fmaf(f1.x, wa.z, p);
    p = fmaf(f1.y, wa.w, p);
    p = fmaf(f2.x, wb.x, p);
    p = fmaf(f2.y, wb.y, p);
    p = fmaf(f3.x, wb.z, p);
    p = fmaf(f3.y, wb.w, p);
    return p;
}

#define EDGE_THREADS 128

__global__ __launch_bounds__(EDGE_THREADS)
void edge_kernel(const int* __restrict__ edge_index,
                 const float* __restrict__ W2,
                 const float* __restrict__ b2,
                 float* __restrict__ out,
                 int E)
{
    const int warp_id = (blockIdx.x * blockDim.x + threadIdx.x) >> 5;
    const int lane = threadIdx.x & 31;
    const int g  = lane >> 3;
    const int gl = lane & 7;

    const long long base = (long long)warp_id * 16 + g * 4;
    if (base >= E) return;

    const int4 rr = *(const int4*)(edge_index + base);
    const int4 cc = *(const int4*)(edge_index + (long long)E + base);

    const size_t o = (size_t)gl * 8;
    const uint4 u0 = *(const uint4*)(g_uv16 + (size_t)rr.x * 128 + o);
    const uint4 v0 = *(const uint4*)(g_uv16 + (size_t)cc.x * 128 + 64 + o);
    const uint4 u1 = *(const uint4*)(g_uv16 + (size_t)rr.y * 128 + o);
    const uint4 v1 = *(const uint4*)(g_uv16 + (size_t)cc.y * 128 + 64 + o);
    const uint4 u2 = *(const uint4*)(g_uv16 + (size_t)rr.z * 128 + o);
    const uint4 v2 = *(const uint4*)(g_uv16 + (size_t)cc.z * 128 + 64 + o);
    const uint4 u3 = *(const uint4*)(g_uv16 + (size_t)rr.w * 128 + o);
    const uint4 v3 = *(const uint4*)(g_uv16 + (size_t)cc.w * 128 + 64 + o);

    const float4 wa = __ldg((const float4*)W2 + gl * 2);
    const float4 wb = __ldg((const float4*)W2 + gl * 2 + 1);

    float p0 = edge_dot(u0, v0, wa, wb);
    float p1 = edge_dot(u1, v1, wa, wb);
    float p2 = edge_dot(u2, v2, wa, wb);
    float p3 = edge_dot(u3, v3, wa, wb);

#pragma unroll
    for (int off = 4; off > 0; off >>= 1) {
        p0 += __shfl_down_sync(0xFFFFFFFFu, p0, off, 8);
        p1 += __shfl_down_sync(0xFFFFFFFFu, p1, off, 8);
        p2 += __shfl_down_sync(0xFFFFFFFFu, p2, off, 8);
        p3 += __shfl_down_sync(0xFFFFFFFFu, p3, off, 8);
    }

    if (gl == 0) {
        float bb = __ldg(b2);
        float4 oo;
        oo.x = 1.0f / (1.0f + __expf(-(p0 + bb)));
        oo.y = 1.0f / (1.0f + __expf(-(p1 + bb)));
        oo.z = 1.0f / (1.0f + __expf(-(p2 + bb)));
        oo.w = 1.0f / (1.0f + __expf(-(p3 + bb)));
        __stcs((float4*)(out + base), oo);   // write-once output, evict-first
    }
}

// ---------------------------------------------------------------------------
extern "C" void kernel_launch(void* const* d_in, const int* in_sizes, int n_in,
                              void* d_out, int out_size)
{
    const float* x          = (const float*)d_in[0];
    const int*   edge_index = (const int*)d_in[1];
    const float* W1         = (const float*)d_in[2];
    const float* b1         = (const float*)d_in[3];
    const float* W2         = (const float*)d_in[4];
    const float* b2         = (const float*)d_in[5];
    float*       out        = (float*)d_out;

    const int n = in_sizes[0] / NODE_DIM;   // 100000
    const int E = in_sizes[1] / 2;          // 625000
    const int tiles = (n + 127) / 128;      // 782

    cudaFuncSetAttribute(node_gemm_persistent,
                         cudaFuncAttributeMaxDynamicSharedMemorySize,
                         (int)GEMM_SMEM);

    node_gemm_persistent<<<GEMM_GRID, 256, GEMM_SMEM>>>(x, W1, b1, n, tiles);

    const int warps_needed = (E + 15) / 16;   // 39063
    const int wpb = EDGE_THREADS / 32;        // 4
    const int edge_blocks = (warps_needed + wpb - 1) / wpb;   // 9766
    edge_kernel<<<edge_blocks, EDGE_THREADS>>>(edge_index, W2, b2, out, E);
}

// round 15
// speedup vs baseline: 1.1001x; 1.0530x over previous
#include <cuda_runtime.h>
#include <cuda_bf16.h>
#include <math.h>
#include <stdint.h>

#define NODE_DIM   128
#define HIDDEN_DIM 64
#define MAX_N      100000

// Scratch UV in bf16: uv16[n][0:64] = u = x[n]@W1[:128]+b1 ; [64:128] = v = x[n]@W1[128:]
__device__ __nv_bfloat16 g_uv16[(size_t)MAX_N * NODE_DIM];

// ---------------------------------------------------------------------------
// PTX helpers
// ---------------------------------------------------------------------------
__device__ __forceinline__ uint32_t smem_u32(const void* p) {
    return (uint32_t)__cvta_generic_to_shared(p);
}
__device__ __forceinline__ void ldsm_x4(uint32_t* r, uint32_t addr) {
    asm volatile("ldmatrix.sync.aligned.m8n8.x4.shared.b16 {%0,%1,%2,%3}, [%4];"
                 : "=r"(r[0]), "=r"(r[1]), "=r"(r[2]), "=r"(r[3]) : "r"(addr));
}
__device__ __forceinline__ void ldsm_x4_t(uint32_t* r, uint32_t addr) {
    asm volatile("ldmatrix.sync.aligned.m8n8.x4.trans.shared.b16 {%0,%1,%2,%3}, [%4];"
                 : "=r"(r[0]), "=r"(r[1]), "=r"(r[2]), "=r"(r[3]) : "r"(addr));
}
__device__ __forceinline__ void mma16816(float* c, const uint32_t* a,
                                         uint32_t b0, uint32_t b1) {
    asm volatile(
        "mma.sync.aligned.m16n8k16.row.col.f32.bf16.bf16.f32 "
        "{%0,%1,%2,%3}, {%4,%5,%6,%7}, {%8,%9}, {%0,%1,%2,%3};"
        : "+f"(c[0]), "+f"(c[1]), "+f"(c[2]), "+f"(c[3])
        : "r"(a[0]), "r"(a[1]), "r"(a[2]), "r"(a[3]), "r"(b0), "r"(b1));
}
__device__ __forceinline__ void cp_async16(uint32_t saddr, const void* g) {
    asm volatile("cp.async.cg.shared.global [%0], [%1], 16;" :: "r"(saddr), "l"(g));
}
__device__ __forceinline__ void cp_commit() {
    asm volatile("cp.async.commit_group;" ::: "memory");
}
__device__ __forceinline__ void cp_wait0() {
    asm volatile("cp.async.wait_group 0;" ::: "memory");
}
// pack float4 -> 2x bf162 (8 bytes)
__device__ __forceinline__ uint2 pack4(float4 v) {
    __nv_bfloat162 h01 = __floats2bfloat162_rn(v.x, v.y);
    __nv_bfloat162 h23 = __floats2bfloat162_rn(v.z, v.w);
    return make_uint2(*(uint32_t*)&h01, *(uint32_t*)&h23);
}

// ---------------------------------------------------------------------------
// Kernel 1: persistent node GEMM (EXACT R8 config — best measured, 20.4 us).
//   UV (N,128) = X (N,128) @ Weff (128,128) + bias(cols 0..63), stored bf16
// cp.async double-buffered raw-float staging, 1 block/SM, 170 KB smem.
// Triggers programmatic launch completion as each block retires.
// ---------------------------------------------------------------------------
#define PAD_COLS 136
#define RAW_BYTES  (128 * 128 * 4)        // 65536
#define EPI_WORDS  68
#define EPI_BYTES  (128 * EPI_WORDS * 4)  // 34816
#define AB_BYTES   (128 * PAD_COLS * 2)   // 34816
#define OFF_EPI    RAW_BYTES
#define OFF_A      (OFF_EPI + EPI_BYTES)
#define OFF_B      (OFF_A + AB_BYTES)
#define GEMM_SMEM  (OFF_B + AB_BYTES)     // 169984

__global__ __launch_bounds__(256, 1)
void node_gemm_persistent(const float* __restrict__ x,
                          const float* __restrict__ W1,
                          const float* __restrict__ b1,
                          int n, int tiles)
{
    extern __shared__ char smraw[];
    float*         Raw = (float*)smraw;
    uint32_t*      Epi = (uint32_t*)(smraw + OFF_EPI);
    __nv_bfloat16* Ah  = (__nv_bfloat16*)(smraw + OFF_A);
    __nv_bfloat16* Bh  = (__nv_bfloat16*)(smraw + OFF_B);

    const int t    = threadIdx.x;
    const int warp = t >> 5;
    const int lane = t & 31;

    // ---- prefetch first tile, then stage W (overlaps latency) ----
    int tile = blockIdx.x;
    if (tile < tiles) {
        const int node0 = tile * 128;
#pragma unroll
        for (int it = 0; it < 16; it++) {
            int idx  = t + it * 256;
            int row  = idx >> 5;
            int node = node0 + row;
            uint32_t sa = smem_u32(Raw) + idx * 16;
            if (node < n)
                cp_async16(sa, (const char*)x + (size_t)node * 512 + (size_t)(idx & 31) * 16);
            else
                *(float4*)((char*)Raw + idx * 16) = make_float4(0.f, 0.f, 0.f, 0.f);
        }
    }
    cp_commit();

    // ---- stage Weff bf16 (once per block) ----
    for (int i = t; i < 128 * 32; i += 256) {
        int k  = i >> 5;
        int c4 = i & 31;
        const float* src = (c4 < 16) ? (W1 + k * 64 + c4 * 4)
                                     : (W1 + (128 + k) * 64 + (c4 - 16) * 4);
        float4 v = *(const float4*)src;
        *(uint2*)(Bh + k * PAD_COLS + c4 * 4) = pack4(v);
    }

    const uint32_t ROWB = PAD_COLS * 2;
    const uint32_t a_base = smem_u32(Ah) +
        (uint32_t)(((warp * 16 + (lane & 15)) * PAD_COLS + (lane >> 4) * 8) * 2);
    const uint32_t b_base = smem_u32(Bh) +
        (uint32_t)(((lane & 15) * PAD_COLS + (lane >> 4) * 8) * 2);

    const int r0  = lane >> 2;
    const int cqh = lane & 3;

    for (; tile < tiles; tile += gridDim.x) {
        const int node0 = tile * 128;

        cp_wait0();
        __syncthreads();

        // ---- convert Raw -> Ah (bf16) ----
#pragma unroll
        for (int it = 0; it < 16; it++) {
            int idx = t + it * 256;
            int row = idx >> 5;
            int c4  = idx & 31;
            float4 v = ((const float4*)Raw)[idx];
            *(uint2*)(Ah + row * PAD_COLS + c4 * 4) = pack4(v);
        }
        __syncthreads();

        // ---- prefetch NEXT tile (overlaps compute) ----
        int tn = tile + gridDim.x;
        if (tn < tiles) {
            const int nn0 = tn * 128;
#pragma unroll
            for (int it = 0; it < 16; it++) {
                int idx  = t + it * 256;
                int row  = idx >> 5;
                int node = nn0 + row;
                uint32_t sa = smem_u32(Raw) + idx * 16;
                if (node < n)
                    cp_async16(sa, (const char*)x + (size_t)node * 512 + (size_t)(idx & 31) * 16);
                else
                    *(float4*)((char*)Raw + idx * 16) = make_float4(0.f, 0.f, 0.f, 0.f);
            }
        }
        cp_commit();

        // ---- compute 128x128 tile (128 HMMA per warp) ----
        float acc[16][4];
#pragma unroll
        for (int i = 0; i < 16; i++)
#pragma unroll
            for (int j = 0; j < 4; j++) acc[i][j] = 0.f;

#pragma unroll
        for (int ks = 0; ks < 8; ks++) {
            uint32_t ah[4];
            ldsm_x4(ah, a_base + ks * 32);
#pragma unroll
            for (int j = 0; j < 8; j++) {
                uint32_t bh[4];
                ldsm_x4_t(bh, b_base + ks * 16 * ROWB + j * 32);
                mma16816(acc[2 * j],     ah, bh[0], bh[1]);
                mma16816(acc[2 * j + 1], ah, bh[2], bh[3]);
            }
        }

        // ---- epilogue: + bias, STS into Epi, coalesced STG ----
        {
            const int lr0 = warp * 16 + r0;
            const int lr1 = lr0 + 8;
#pragma unroll
            for (int nt = 0; nt < 16; nt++) {
                int col = nt * 8 + cqh * 2;
                float bx = (col < 64) ? __ldg(b1 + col) : 0.f;
                float by = (col < 64) ? __ldg(b1 + col + 1) : 0.f;
                __nv_bfloat162 p0 = __floats2bfloat162_rn(acc[nt][0] + bx, acc[nt][1] + by);
                __nv_bfloat162 p1 = __floats2bfloat162_rn(acc[nt][2] + bx, acc[nt][3] + by);
                Epi[lr0 * EPI_WORDS + nt * 4 + cqh] = *(uint32_t*)&p0;
                Epi[lr1 * EPI_WORDS + nt * 4 + cqh] = *(uint32_t*)&p1;
            }
        }
        __syncthreads();

#pragma unroll
        for (int it = 0; it < 8; it++) {
            int idx = t + it * 256;
            int row = idx >> 4;
            int wq  = idx & 15;
            int node = node0 + row;
            if (node < n) {
                uint4 v = *(const uint4*)(Epi + row * EPI_WORDS + wq * 4);
                *(uint4*)(g_uv16 + (size_t)node * 128 + wq * 8) = v;
            }
        }
    }

    // allow the dependent edge kernel to begin launching as we retire
    cudaTriggerProgrammaticLaunchCompletion();
}

// ---------------------------------------------------------------------------
// Kernel 2: edge pass (EXACT R8 config — best measured, 20.9 us) + PDL.
// Preloads indices and weights (independent of UV), then grid-syncs on the
// GEMM before gathering.
// ---------------------------------------------------------------------------
__device__ __forceinline__ float edge_dot(uint4 u, uint4 v, float4 wa, float4 wb)
{
    const __nv_bfloat162 z2 = __float2bfloat162_rn(0.f);
    __nv_bfloat162 h0 = __hmax2(__hadd2(*(__nv_bfloat162*)&u.x, *(__nv_bfloat162*)&v.x), z2);
    __nv_bfloat162 h1 = __hmax2(__hadd2(*(__nv_bfloat162*)&u.y, *(__nv_bfloat162*)&v.y), z2);
    __nv_bfloat162 h2 = __hmax2(__hadd2(*(__nv_bfloat162*)&u.z, *(__nv_bfloat162*)&v.z), z2);
    __nv_bfloat162 h3 = __hmax2(__hadd2(*(__nv_bfloat162*)&u.w, *(__nv_bfloat162*)&v.w), z2);
    float2 f0 = __bfloat1622float2(h0);
    float2 f1 = __bfloat1622float2(h1);
    float2 f2 = __bfloat1622float2(h2);
    float2 f3 = __bfloat1622float2(h3);
    float p = f0.x * wa.x;
    p = fmaf(f0.y, wa.y, p);
    p = fmaf(f1.x, wa.z, p);
    p = fmaf(f1.y, wa.w, p);
    p = fmaf(f2.x, wb.x, p);
    p = fmaf(f2.y, wb.y, p);
    p = fmaf(f3.x, wb.z, p);
    p = fmaf(f3.y, wb.w, p);
    return p;
}

__global__ void edge_kernel(const int* __restrict__ edge_index,
                            const float* __restrict__ W2,
                            const float* __restrict__ b2,
                            float* __restrict__ out,
                            int E)
{
    const int warp_id = (blockIdx.x * blockDim.x + threadIdx.x) >> 5;
    const int lane = threadIdx.x & 31;
    const int g  = lane >> 3;
    const int gl = lane & 7;

    const long long base = (long long)warp_id * 16 + g * 4;
    if (base >= E) { cudaGridDependencySynchronize(); return; }

    // ---- preamble independent of the GEMM output: overlaps GEMM tail ----
    const int4 rr = *(const int4*)(edge_index + base);
    const int4 cc = *(const int4*)(edge_index + (long long)E + base);
    const float4 wa = __ldg((const float4*)W2 + gl * 2);
    const float4 wb = __ldg((const float4*)W2 + gl * 2 + 1);
    const float  bb = __ldg(b2);

    // wait for the full GEMM grid (UV visible) before gathering
    cudaGridDependencySynchronize();

    const size_t o = (size_t)gl * 8;
    const uint4 u0 = *(const uint4*)(g_uv16 + (size_t)rr.x * 128 + o);
    const uint4 v0 = *(const uint4*)(g_uv16 + (size_t)cc.x * 128 + 64 + o);
    const uint4 u1 = *(const uint4*)(g_uv16 + (size_t)rr.y * 128 + o);
    const uint4 v1 = *(const uint4*)(g_uv16 + (size_t)cc.y * 128 + 64 + o);
    const uint4 u2 = *(const uint4*)(g_uv16 + (size_t)rr.z * 128 + o);
    const uint4 v2 = *(const uint4*)(g_uv16 + (size_t)cc.z * 128 + 64 + o);
    const uint4 u3 = *(const uint4*)(g_uv16 + (size_t)rr.w * 128 + o);
    const uint4 v3 = *(const uint4*)(g_uv16 + (size_t)cc.w * 128 + 64 + o);

    float p0 = edge_dot(u0, v0, wa, wb);
    float p1 = edge_dot(u1, v1, wa, wb);
    float p2 = edge_dot(u2, v2, wa, wb);
    float p3 = edge_dot(u3, v3, wa, wb);

#pragma unroll
    for (int off = 4; off > 0; off >>= 1) {
        p0 += __shfl_down_sync(0xFFFFFFFFu, p0, off, 8);
        p1 += __shfl_down_sync(0xFFFFFFFFu, p1, off, 8);
        p2 += __shfl_down_sync(0xFFFFFFFFu, p2, off, 8);
        p3 += __shfl_down_sync(0xFFFFFFFFu, p3, off, 8);
    }

    if (gl == 0) {
        float4 oo;
        oo.x = 1.0f / (1.0f + __expf(-(p0 + bb)));
        oo.y = 1.0f / (1.0f + __expf(-(p1 + bb)));
        oo.z = 1.0f / (1.0f + __expf(-(p2 + bb)));
        oo.w = 1.0f / (1.0f + __expf(-(p3 + bb)));
        *(float4*)(out + base) = oo;
    }
}

// ---------------------------------------------------------------------------
extern "C" void kernel_launch(void* const* d_in, const int* in_sizes, int n_in,
                              void* d_out, int out_size)
{
    const float* x          = (const float*)d_in[0];
    const int*   edge_index = (const int*)d_in[1];
    const float* W1         = (const float*)d_in[2];
    const float* b1         = (const float*)d_in[3];
    const float* W2         = (const float*)d_in[4];
    const float* b2         = (const float*)d_in[5];
    float*       out        = (float*)d_out;

    const int n = in_sizes[0] / NODE_DIM;   // 100000
    const int E = in_sizes[1] / 2;          // 625000
    const int tiles = (n + 127) / 128;      // 782

    cudaFuncSetAttribute(node_gemm_persistent,
                         cudaFuncAttributeMaxDynamicSharedMemorySize,
                         (int)GEMM_SMEM);

    node_gemm_persistent<<<148, 256, GEMM_SMEM>>>(x, W1, b1, n, tiles);

    // edge kernel with Programmatic Dependent Launch (overlaps GEMM tail)
    const int warps_needed = (E + 15) / 16;                 // 39063
    const int threads = 256;
    const int edge_blocks = (warps_needed + (threads / 32) - 1) / (threads / 32);  // 4883

    cudaLaunchConfig_t cfg = {};
    cfg.gridDim  = dim3((unsigned)edge_blocks, 1, 1);
    cfg.blockDim = dim3((unsigned)threads, 1, 1);
    cfg.dynamicSmemBytes = 0;
    cfg.stream = 0;
    cudaLaunchAttribute attrs[1];
    attrs[0].id = cudaLaunchAttributeProgrammaticStreamSerialization;
    attrs[0].val.programmaticStreamSerializationAllowed = 1;
    cfg.attrs = attrs;
    cfg.numAttrs = 1;
    cudaLaunchKernelEx(&cfg, edge_kernel, edge_index, W2, b2, out, E);
}